// round 14
// baseline (speedup 1.0000x reference)
#include <cuda_runtime.h>
#include <float.h>

// ROI max pooling, exact integer-bin partition (matches reference):
//   cell (py,px) of roi (y0,x0,h,w) covers rows [y0 + py*h/7, y0 + (py+1)*h/7)
//   and cols [x0 + px*w/7, x0 + (px+1)*w/7). h,w >= 7 so cells are non-empty.
//
// Shapes: feature_map [B=2, H=38, W=38, C=512] f32, rois [B=2, N=64, 4] i32,
// out [B, N, 7, 7, C] f32.
//
// R12 -> R13: config sweep brackets R4 (2 f4/thread, 1-warp blocks) as the
// local optimum; occupancy/MLP/fatness all falsified. Remaining structural
// lever: the scheduling tail. Block durations span 36:1 (cell = 1..36 px,
// ~3us for the biggest); random order can start a 3us block at the end of
// the last wave. Fix = LPT: a tiny pre-kernel ranks rois by descending h*w
// (O(n^2), 1 block, <1us) into g_order; the R4-body main kernel processes
// rois in that order so stragglers start at t=0 and the launch tail is all
// 1-px cells.

#define H_DIM 38
#define W_DIM 38
#define C4 128           // C/4 float4 groups per pixel
#define POOL 7
#define ROWSTRIDE (W_DIM * C4)
#define MAX_ROIS 256

__device__ int g_order[MAX_ROIS];

__global__ void order_kernel(const int* __restrict__ rois, int n_rois) {
    __shared__ int keys[MAX_ROIS];
    const int i = threadIdx.x;
    if (i < n_rois)
        keys[i] = rois[4 * i + 2] * rois[4 * i + 3];   // h*w
    __syncthreads();
    if (i < n_rois) {
        const int k = keys[i];
        int rank = 0;
        for (int j = 0; j < n_rois; ++j) {
            const int kj = keys[j];
            rank += (kj > k) || (kj == k && j < i);    // descending, stable
        }
        g_order[rank] = i;
    }
}

__device__ __forceinline__ void fmax4(float4& m, const float4 v) {
    m.x = fmaxf(m.x, v.x);
    m.y = fmaxf(m.y, v.y);
    m.z = fmaxf(m.z, v.z);
    m.w = fmaxf(m.w, v.w);
}

__global__ __launch_bounds__(32) void roi_pool_kernel(
    const float4* __restrict__ fm,   // [B, H, W, C/4] as float4
    const int*    __restrict__ rois, // [B*N, 4] (y, x, h, w)
    float4*       __restrict__ out,  // [B*N, 49, C/4] as float4
    int n_per_b)                     // N (rois per batch)
{
    const int slot = blockIdx.x;        // ord*49 + py*7 + px
    const int px   = slot % POOL;
    const int py   = (slot / POOL) % POOL;
    const int ord  = slot / (POOL * POOL);
    const int roi  = g_order[ord];      // LPT: biggest rois first
    const int b    = roi / n_per_b;

    const int4 r = __ldg((const int4*)(rois + roi * 4));
    const int y0 = r.x, x0 = r.y, h = r.z, w = r.w;

    const int ys = y0 + (py * h) / POOL;
    const int ye = y0 + ((py + 1) * h) / POOL;
    const int xs = x0 + (px * w) / POOL;
    const int xe = x0 + ((px + 1) * w) / POOL;

    // channel half: block gy handles float4 slots [gy*64, gy*64+64)
    const int c = (blockIdx.y << 6) + threadIdx.x;
    const float4* base = fm + ((size_t)b * H_DIM * W_DIM) * C4 + c;

    float4 m0 = make_float4(-FLT_MAX, -FLT_MAX, -FLT_MAX, -FLT_MAX);
    float4 m1 = m0;

    int y = ys;
    // ---- y-unroll 2, x-unroll 2: 8 independent LDG.128 per iteration ----
    for (; y + 1 < ye; y += 2) {
        const float4* p0 = base + ((size_t)(y * W_DIM + xs)) * C4;
        const float4* p1 = p0 + ROWSTRIDE;
        int x = xs;
        for (; x + 1 < xe; x += 2, p0 += 2 * C4, p1 += 2 * C4) {
            float4 a0 = __ldg(p0);
            float4 a1 = __ldg(p0 + 32);
            float4 a2 = __ldg(p0 + C4);
            float4 a3 = __ldg(p0 + C4 + 32);
            float4 b0 = __ldg(p1);
            float4 b1 = __ldg(p1 + 32);
            float4 b2 = __ldg(p1 + C4);
            float4 b3 = __ldg(p1 + C4 + 32);
            fmax4(m0, a0); fmax4(m1, a1);
            fmax4(m0, a2); fmax4(m1, a3);
            fmax4(m0, b0); fmax4(m1, b1);
            fmax4(m0, b2); fmax4(m1, b3);
        }
        if (x < xe) {
            float4 a0 = __ldg(p0);
            float4 a1 = __ldg(p0 + 32);
            float4 b0 = __ldg(p1);
            float4 b1 = __ldg(p1 + 32);
            fmax4(m0, a0); fmax4(m1, a1);
            fmax4(m0, b0); fmax4(m1, b1);
        }
    }
    // ---- remainder row (odd cell height), x-unroll 2 ----
    if (y < ye) {
        const float4* p0 = base + ((size_t)(y * W_DIM + xs)) * C4;
        int x = xs;
        for (; x + 1 < xe; x += 2, p0 += 2 * C4) {
            float4 a0 = __ldg(p0);
            float4 a1 = __ldg(p0 + 32);
            float4 a2 = __ldg(p0 + C4);
            float4 a3 = __ldg(p0 + C4 + 32);
            fmax4(m0, a0); fmax4(m1, a1);
            fmax4(m0, a2); fmax4(m1, a3);
        }
        if (x < xe) {
            float4 a0 = __ldg(p0);
            float4 a1 = __ldg(p0 + 32);
            fmax4(m0, a0); fmax4(m1, a1);
        }
    }

    // output goes to the REAL roi's slot
    const int cell = roi * (POOL * POOL) + py * POOL + px;
    float4* o = out + (size_t)cell * C4 + c;
    o[0]  = m0;
    o[32] = m1;
}

extern "C" void kernel_launch(void* const* d_in, const int* in_sizes, int n_in,
                              void* d_out, int out_size) {
    const float4* fm   = (const float4*)d_in[0];
    const int*    rois = (const int*)d_in[1];
    float4*       out  = (float4*)d_out;

    const int n_rois  = in_sizes[1] / 4;     // B*N = 128
    const int B       = 2;                   // fixed per problem shapes
    const int n_per_b = n_rois / B;          // N = 64

    order_kernel<<<1, MAX_ROIS>>>(rois, n_rois);

    dim3 grid(n_rois * POOL * POOL, 2);      // 6272 cells x 2 channel halves
    roi_pool_kernel<<<grid, 32>>>(fm, rois, out, n_per_b);
}

// round 15
// speedup vs baseline: 1.3233x; 1.3233x over previous
#include <cuda_runtime.h>
#include <float.h>

// ROI max pooling, exact integer-bin partition (matches reference):
//   cell (py,px) of roi (y0,x0,h,w) covers rows [y0 + py*h/7, y0 + (py+1)*h/7)
//   and cols [x0 + px*w/7, x0 + (px+1)*w/7). h,w >= 7 so cells are non-empty.
//
// Shapes: feature_map [B=2, H=38, W=38, C=512] f32, rois [B=2, N=64, 4] i32,
// out [B, N, 7, 7, C] f32.
//
// R13 -> R14: LPT falsified (indirection on the prologue path + extra launch
// node cost 4us of bench). Back to single-launch R4 body (proven optimum:
// 1-warp blocks, 2 f4/thread, y2x2 unroll). This round shortens the serial
// per-block prologue: 3D grid (14, 7, 128) makes px/half/py/roi pure blockIdx
// bit ops (no div/mod-by-7/49 IMAD chains before the roi load), batch index
// is one compare. Body unchanged.

#define H_DIM 38
#define W_DIM 38
#define C4 128           // C/4 float4 groups per pixel
#define POOL 7
#define ROWSTRIDE (W_DIM * C4)

__device__ __forceinline__ void fmax4(float4& m, const float4 v) {
    m.x = fmaxf(m.x, v.x);
    m.y = fmaxf(m.y, v.y);
    m.z = fmaxf(m.z, v.z);
    m.w = fmaxf(m.w, v.w);
}

__global__ __launch_bounds__(32) void roi_pool_kernel(
    const float4* __restrict__ fm,   // [B, H, W, C/4] as float4
    const int*    __restrict__ rois, // [B*N, 4] (y, x, h, w)
    float4*       __restrict__ out,  // [B*N, 49, C/4] as float4
    int n_per_b)                     // N (rois per batch)
{
    // grid: x = px*2 + channel_half (14), y = py (7), z = roi (B*N)
    const int half = blockIdx.x & 1;
    const int px   = blockIdx.x >> 1;
    const int py   = blockIdx.y;
    const int roi  = blockIdx.z;
    const int b    = (roi >= n_per_b) ? 1 : 0;

    const int4 r = __ldg((const int4*)(rois + roi * 4));
    const int y0 = r.x, x0 = r.y, h = r.z, w = r.w;

    const int ys = y0 + (py * h) / POOL;
    const int ye = y0 + ((py + 1) * h) / POOL;
    const int xs = x0 + (px * w) / POOL;
    const int xe = x0 + ((px + 1) * w) / POOL;

    // channel half: float4 slots [half*64, half*64+64); thread owns c, c+32
    const int c = (half << 6) + threadIdx.x;
    const float4* base = fm + ((size_t)b * H_DIM * W_DIM) * C4 + c;

    float4 m0 = make_float4(-FLT_MAX, -FLT_MAX, -FLT_MAX, -FLT_MAX);
    float4 m1 = m0;

    int y = ys;
    // ---- y-unroll 2, x-unroll 2: 8 independent LDG.128 per iteration ----
    for (; y + 1 < ye; y += 2) {
        const float4* p0 = base + ((size_t)(y * W_DIM + xs)) * C4;
        const float4* p1 = p0 + ROWSTRIDE;
        int x = xs;
        for (; x + 1 < xe; x += 2, p0 += 2 * C4, p1 += 2 * C4) {
            float4 a0 = __ldg(p0);
            float4 a1 = __ldg(p0 + 32);
            float4 a2 = __ldg(p0 + C4);
            float4 a3 = __ldg(p0 + C4 + 32);
            float4 b0 = __ldg(p1);
            float4 b1 = __ldg(p1 + 32);
            float4 b2 = __ldg(p1 + C4);
            float4 b3 = __ldg(p1 + C4 + 32);
            fmax4(m0, a0); fmax4(m1, a1);
            fmax4(m0, a2); fmax4(m1, a3);
            fmax4(m0, b0); fmax4(m1, b1);
            fmax4(m0, b2); fmax4(m1, b3);
        }
        if (x < xe) {
            float4 a0 = __ldg(p0);
            float4 a1 = __ldg(p0 + 32);
            float4 b0 = __ldg(p1);
            float4 b1 = __ldg(p1 + 32);
            fmax4(m0, a0); fmax4(m1, a1);
            fmax4(m0, b0); fmax4(m1, b1);
        }
    }
    // ---- remainder row (odd cell height), x-unroll 2 ----
    if (y < ye) {
        const float4* p0 = base + ((size_t)(y * W_DIM + xs)) * C4;
        int x = xs;
        for (; x + 1 < xe; x += 2, p0 += 2 * C4) {
            float4 a0 = __ldg(p0);
            float4 a1 = __ldg(p0 + 32);
            float4 a2 = __ldg(p0 + C4);
            float4 a3 = __ldg(p0 + C4 + 32);
            fmax4(m0, a0); fmax4(m1, a1);
            fmax4(m0, a2); fmax4(m1, a3);
        }
        if (x < xe) {
            float4 a0 = __ldg(p0);
            float4 a1 = __ldg(p0 + 32);
            fmax4(m0, a0); fmax4(m1, a1);
        }
    }

    const int cell = (roi * POOL + py) * POOL + px;
    float4* o = out + (size_t)cell * C4 + c;
    o[0]  = m0;
    o[32] = m1;
}

extern "C" void kernel_launch(void* const* d_in, const int* in_sizes, int n_in,
                              void* d_out, int out_size) {
    const float4* fm   = (const float4*)d_in[0];
    const int*    rois = (const int*)d_in[1];
    float4*       out  = (float4*)d_out;

    const int n_rois  = in_sizes[1] / 4;     // B*N = 128
    const int B       = 2;                   // fixed per problem shapes
    const int n_per_b = n_rois / B;          // N = 64

    dim3 grid(POOL * 2, POOL, n_rois);       // (14, 7, 128)
    roi_pool_kernel<<<grid, 32>>>(fm, rois, out, n_per_b);
}